// round 2
// baseline (speedup 1.0000x reference)
#include <cuda_runtime.h>
#include <mma.h>
#include <math.h>

using namespace nvcuda;

#define BB  16
#define CC  128
#define PP  48
#define NN  2304
#define CQ  16          // C/8
#define BCN (BB*CC*NN)  // 4718592

// ---------------- scratch (device globals; no allocation allowed) ----------------
__device__ float g_mean[CC], g_rstd[CC];
__device__ float g_xn[BCN];
__device__ float g_t1[BCN];
__device__ float g_feat[BCN];
__device__ float g_v[BCN];                   // (B, C, N)
__device__ float g_Vout[BCN];                // (B, N, C)  attention output, transposed
__device__ float g_T[BCN];
__device__ float g_fr[BCN];
__device__ float g_q[BB*NN*CQ];              // (B, N, 16)
__device__ float g_k[BB*NN*CQ];              // (B, N, 16)
__device__ float g_energy[(size_t)BB*NN*NN]; // (B, N, N) ~340MB

// ---------------- cp.async helpers ----------------
__device__ __forceinline__ void cp_async16(void* smem, const void* gmem) {
    unsigned s = (unsigned)__cvta_generic_to_shared(smem);
    asm volatile("cp.async.cg.shared.global [%0], [%1], 16;\n" :: "r"(s), "l"(gmem));
}
__device__ __forceinline__ void cp_commit() { asm volatile("cp.async.commit_group;\n"); }
template<int n> __device__ __forceinline__ void cp_wait() { asm volatile("cp.async.wait_group %0;\n" :: "n"(n)); }

// ---------------- batchnorm ----------------
__global__ void bn_stats_kernel(const float* __restrict__ x) {
    int c = blockIdx.x;
    float s1 = 0.f, s2 = 0.f;
    for (int idx = threadIdx.x; idx < BB*NN; idx += 256) {
        int b = idx / NN, n = idx - b*NN;
        float v = x[((size_t)b*CC + c)*NN + n];
        s1 += v; s2 += v*v;
    }
    __shared__ float r1[256], r2[256];
    r1[threadIdx.x] = s1; r2[threadIdx.x] = s2;
    __syncthreads();
    for (int s = 128; s > 0; s >>= 1) {
        if (threadIdx.x < s) { r1[threadIdx.x] += r1[threadIdx.x+s]; r2[threadIdx.x] += r2[threadIdx.x+s]; }
        __syncthreads();
    }
    if (threadIdx.x == 0) {
        const float inv = 1.f / (float)(BB*NN);
        float m = r1[0] * inv;
        float var = r2[0] * inv - m*m;
        g_mean[c] = m;
        g_rstd[c] = rsqrtf(var + 1e-5f);
    }
}

__global__ void bn_apply_kernel(const float* __restrict__ x, const float* __restrict__ gam,
                                const float* __restrict__ bet, float* __restrict__ y) {
    int idx = blockIdx.x*256 + threadIdx.x;
    int c = (idx / NN) % CC;
    y[idx] = (x[idx] - g_mean[c]) * g_rstd[c] * gam[c] + bet[c];
}

// ================= pipelined TF32 GEMM: C[m,n] = op(sum_k A[m,k]*W[n,k] + bias[n]) =================
// requires K % 32 == 0, M % 128 == 0, Nn % 128 == 0
// grid (Nn/128, M/128, batch), 256 threads (8 warps, 2x4)
#define GBM 128
#define GBN 128
#define GBK 32
#define GSTG 3
#define GLDA 36
#define GSMEM (GSTG*2*GBM*GLDA*4)   // 110592 bytes

template<bool RELU>
__global__ __launch_bounds__(256) void gemm_pipe_kernel(
    const float* __restrict__ A, const float* __restrict__ W,
    const float* __restrict__ bias, float* __restrict__ Cc,
    int M, int Nn, int K, size_t sA, size_t sW, size_t sC)
{
    extern __shared__ float sm[];
    float* sAb = sm;
    float* sWb = sm + GSTG*GBM*GLDA;
    const int tid  = threadIdx.x;
    const int warp = tid >> 5, lane = tid & 31;
    const int wm = warp & 1;   // 2 warp-rows of 64
    const int wn = warp >> 1;  // 4 warp-cols of 32

    A  += (size_t)blockIdx.z*sA + (size_t)blockIdx.y*GBM*K;
    W  += (size_t)blockIdx.z*sW + (size_t)blockIdx.x*GBN*K;
    Cc += (size_t)blockIdx.z*sC + (size_t)blockIdx.y*GBM*(size_t)Nn + (size_t)blockIdx.x*GBN;

    const int ktiles = K / GBK;

    auto load_stage = [&](int kt, int s) {
        const int k0 = kt * GBK;
        float* da = sAb + s*GBM*GLDA;
        float* db = sWb + s*GBM*GLDA;
        #pragma unroll
        for (int i = 0; i < 4; i++) {
            int idx = tid + i*256;       // 0..1023
            int row = idx >> 3;          // 0..127
            int c4  = (idx & 7) << 2;    // 0..28
            cp_async16(da + row*GLDA + c4, A + (size_t)row*K + k0 + c4);
            cp_async16(db + row*GLDA + c4, W + (size_t)row*K + k0 + c4);
        }
        cp_commit();
    };

    wmma::fragment<wmma::accumulator,16,16,8,float> acc[4][2];
    #pragma unroll
    for (int i = 0; i < 4; i++)
        #pragma unroll
        for (int j = 0; j < 2; j++)
            wmma::fill_fragment(acc[i][j], 0.f);

    #pragma unroll
    for (int s = 0; s < GSTG-1; s++) {
        if (s < ktiles) load_stage(s, s); else cp_commit();
    }

    for (int kt = 0; kt < ktiles; kt++) {
        const int s = kt % GSTG;
        cp_wait<GSTG-2>();
        __syncthreads();
        if (kt + GSTG-1 < ktiles) load_stage(kt + GSTG-1, (kt + GSTG-1) % GSTG);
        else cp_commit();

        const float* a0 = sAb + s*GBM*GLDA;
        const float* b0 = sWb + s*GBM*GLDA;
        #pragma unroll
        for (int kk = 0; kk < 4; kk++) {
            wmma::fragment<wmma::matrix_a,16,16,8,wmma::precision::tf32,wmma::row_major> af[4];
            wmma::fragment<wmma::matrix_b,16,16,8,wmma::precision::tf32,wmma::col_major> bf[2];
            #pragma unroll
            for (int i = 0; i < 4; i++) {
                wmma::load_matrix_sync(af[i], a0 + (wm*64 + i*16)*GLDA + kk*8, GLDA);
                #pragma unroll
                for (int t = 0; t < af[i].num_elements; t++)
                    af[i].x[t] = wmma::__float_to_tf32(af[i].x[t]);
            }
            #pragma unroll
            for (int j = 0; j < 2; j++) {
                wmma::load_matrix_sync(bf[j], b0 + (wn*32 + j*16)*GLDA + kk*8, GLDA);
                #pragma unroll
                for (int t = 0; t < bf[j].num_elements; t++)
                    bf[j].x[t] = wmma::__float_to_tf32(bf[j].x[t]);
            }
            #pragma unroll
            for (int i = 0; i < 4; i++)
                #pragma unroll
                for (int j = 0; j < 2; j++)
                    wmma::mma_sync(acc[i][j], af[i], bf[j], acc[i][j]);
        }
        __syncthreads();
    }

    // epilogue: stage each 16x16 fragment through per-warp smem, vectorized stores
    __syncthreads();
    float* st = sm + warp*256;
    const int row  = lane >> 1;
    const int half = lane & 1;
    #pragma unroll
    for (int i = 0; i < 4; i++) {
        #pragma unroll
        for (int j = 0; j < 2; j++) {
            wmma::store_matrix_sync(st, acc[i][j], 16, wmma::mem_row_major);
            __syncwarp();
            const int gr0 = wm*64 + i*16;
            const int gc0 = wn*32 + j*16;
            float4 v0 = *reinterpret_cast<const float4*>(st + row*16 + half*8);
            float4 v1 = *reinterpret_cast<const float4*>(st + row*16 + half*8 + 4);
            if (bias) {
                const float* bp = bias + blockIdx.x*GBN + gc0 + half*8;
                float4 b0 = *reinterpret_cast<const float4*>(bp);
                float4 b1 = *reinterpret_cast<const float4*>(bp + 4);
                v0.x += b0.x; v0.y += b0.y; v0.z += b0.z; v0.w += b0.w;
                v1.x += b1.x; v1.y += b1.y; v1.z += b1.z; v1.w += b1.w;
            }
            if (RELU) {
                v0.x = fmaxf(v0.x, 0.f); v0.y = fmaxf(v0.y, 0.f); v0.z = fmaxf(v0.z, 0.f); v0.w = fmaxf(v0.w, 0.f);
                v1.x = fmaxf(v1.x, 0.f); v1.y = fmaxf(v1.y, 0.f); v1.z = fmaxf(v1.z, 0.f); v1.w = fmaxf(v1.w, 0.f);
            }
            float* op = Cc + (size_t)(gr0 + row)*Nn + gc0 + half*8;
            *reinterpret_cast<float4*>(op)     = v0;
            *reinterpret_cast<float4*>(op + 4) = v1;
            __syncwarp();
        }
    }
}

// ---------------- legacy single-stage GEMM (used for K=16 energy GEMM only) ----------------
#define LBK 16
#define LLD 20

template<bool RELU>
__global__ __launch_bounds__(256) void gemm_abt_kernel(
    const float* __restrict__ A, const float* __restrict__ W,
    const float* __restrict__ bias, float* __restrict__ Cc,
    int M, int Nn, int K, size_t sA, size_t sW, size_t sC)
{
    __shared__ float As[GBM*LLD];
    __shared__ float Ws[GBN*LLD];
    const int tid  = threadIdx.x;
    const int warp = tid >> 5, lane = tid & 31;
    const int wm = warp & 1;
    const int wn = warp >> 1;

    A  += (size_t)blockIdx.z*sA + (size_t)blockIdx.y*GBM*K;
    W  += (size_t)blockIdx.z*sW + (size_t)blockIdx.x*GBN*K;
    Cc += (size_t)blockIdx.z*sC + (size_t)blockIdx.y*GBM*Nn + (size_t)blockIdx.x*GBN;

    wmma::fragment<wmma::accumulator,16,16,8,float> acc[4][2];
    #pragma unroll
    for (int i = 0; i < 4; i++)
        #pragma unroll
        for (int j = 0; j < 2; j++)
            wmma::fill_fragment(acc[i][j], 0.f);

    for (int k0 = 0; k0 < K; k0 += LBK) {
        #pragma unroll
        for (int i = 0; i < 2; i++) {
            int idx = tid + i*256;
            int row = idx >> 2;
            int c4  = (idx & 3) << 2;
            float4 va = *reinterpret_cast<const float4*>(A + (size_t)row*K + k0 + c4);
            float4 vb = *reinterpret_cast<const float4*>(W + (size_t)row*K + k0 + c4);
            float* da = As + row*LLD + c4;
            float* db = Ws + row*LLD + c4;
            da[0] = wmma::__float_to_tf32(va.x); da[1] = wmma::__float_to_tf32(va.y);
            da[2] = wmma::__float_to_tf32(va.z); da[3] = wmma::__float_to_tf32(va.w);
            db[0] = wmma::__float_to_tf32(vb.x); db[1] = wmma::__float_to_tf32(vb.y);
            db[2] = wmma::__float_to_tf32(vb.z); db[3] = wmma::__float_to_tf32(vb.w);
        }
        __syncthreads();
        #pragma unroll
        for (int kk = 0; kk < 2; kk++) {
            wmma::fragment<wmma::matrix_a,16,16,8,wmma::precision::tf32,wmma::row_major> af[4];
            wmma::fragment<wmma::matrix_b,16,16,8,wmma::precision::tf32,wmma::col_major> bf[2];
            #pragma unroll
            for (int i = 0; i < 4; i++)
                wmma::load_matrix_sync(af[i], As + (wm*64 + i*16)*LLD + kk*8, LLD);
            #pragma unroll
            for (int j = 0; j < 2; j++)
                wmma::load_matrix_sync(bf[j], Ws + (wn*32 + j*16)*LLD + kk*8, LLD);
            #pragma unroll
            for (int i = 0; i < 4; i++)
                #pragma unroll
                for (int j = 0; j < 2; j++)
                    wmma::mma_sync(acc[i][j], af[i], bf[j], acc[i][j]);
        }
        __syncthreads();
    }

    float* st = As + warp*256;
    const int row  = lane >> 1;
    const int half = lane & 1;
    #pragma unroll
    for (int i = 0; i < 4; i++) {
        #pragma unroll
        for (int j = 0; j < 2; j++) {
            wmma::store_matrix_sync(st, acc[i][j], 16, wmma::mem_row_major);
            __syncwarp();
            const int gr0 = wm*64 + i*16;
            const int gc0 = wn*32 + j*16;
            float4 v0 = *reinterpret_cast<const float4*>(st + row*16 + half*8);
            float4 v1 = *reinterpret_cast<const float4*>(st + row*16 + half*8 + 4);
            if (bias) {
                const float* bp = bias + blockIdx.x*GBN + gc0 + half*8;
                float4 b0 = *reinterpret_cast<const float4*>(bp);
                float4 b1 = *reinterpret_cast<const float4*>(bp + 4);
                v0.x += b0.x; v0.y += b0.y; v0.z += b0.z; v0.w += b0.w;
                v1.x += b1.x; v1.y += b1.y; v1.z += b1.z; v1.w += b1.w;
            }
            if (RELU) {
                v0.x = fmaxf(v0.x, 0.f); v0.y = fmaxf(v0.y, 0.f); v0.z = fmaxf(v0.z, 0.f); v0.w = fmaxf(v0.w, 0.f);
                v1.x = fmaxf(v1.x, 0.f); v1.y = fmaxf(v1.y, 0.f); v1.z = fmaxf(v1.z, 0.f); v1.w = fmaxf(v1.w, 0.f);
            }
            float* op = Cc + (size_t)(gr0 + row)*Nn + gc0 + half*8;
            *reinterpret_cast<float4*>(op)     = v0;
            *reinterpret_cast<float4*>(op + 4) = v1;
            __syncwarp();
        }
    }
}

// ---------------- conv1x1 (channel mix), optional concat input, optional transposed output ----------
__global__ __launch_bounds__(256) void conv1x1_kernel(
    const float* __restrict__ X1, const float* __restrict__ X2,
    const float* __restrict__ W, const float* __restrict__ bias,
    float* __restrict__ out, int Cin1, int Cin2, int Cout, int outT)
{
    __shared__ float s1[CC*33];
    __shared__ float s2[CC*33];
    const int b  = blockIdx.y;
    const int n0 = blockIdx.x * 32;
    const int tid = threadIdx.y*32 + threadIdx.x;

    for (int idx = tid; idx < Cin1*32; idx += 256) {
        int c = idx >> 5, n = idx & 31;
        s1[c*33 + n] = X1[((size_t)b*Cin1 + c)*NN + n0 + n];
    }
    if (X2) {
        for (int idx = tid; idx < 32*Cin2; idx += 256) {
            int n = idx >> 7, c = idx & 127;   // Cin2 == 128
            s2[c*33 + n] = X2[((size_t)b*NN + n0 + n)*(size_t)Cin2 + c];
        }
    }
    __syncthreads();

    const int nx = threadIdx.x, ty = threadIdx.y;
    const int Ct = Cin1 + Cin2;
    for (int ob = 0; ob < Cout; ob += 32) {
        const int nacc = (Cout - ob) >= 32 ? 4 : ((Cout - ob + 7) >> 3);
        float acc[4];
        #pragma unroll
        for (int u = 0; u < 4; u++) acc[u] = (u < nacc) ? bias[ob + ty + 8*u] : 0.f;
        for (int c = 0; c < Cin1; c++) {
            float xv = s1[c*33 + nx];
            #pragma unroll
            for (int u = 0; u < 4; u++)
                if (u < nacc) acc[u] += W[(size_t)(ob + ty + 8*u)*Ct + c] * xv;
        }
        if (X2) {
            for (int c = 0; c < Cin2; c++) {
                float xv = s2[c*33 + nx];
                #pragma unroll
                for (int u = 0; u < 4; u++)
                    if (u < nacc) acc[u] += W[(size_t)(ob + ty + 8*u)*Ct + Cin1 + c] * xv;
            }
        }
        #pragma unroll
        for (int u = 0; u < 4; u++) if (u < nacc) {
            int o = ob + ty + 8*u;
            if (outT) out[((size_t)b*NN + n0 + nx)*(size_t)Cout + o] = acc[u];
            else      out[((size_t)b*Cout + o)*(size_t)NN + n0 + nx] = acc[u];
        }
    }
}

// ---------------- row softmax over last dim, with pre-scale ----------------
__global__ void softmax_kernel(float* __restrict__ E, float scale) {
    float* p = E + (size_t)blockIdx.x * NN;
    const int t = threadIdx.x;
    float r[9];
    float mx = -1e30f;
    #pragma unroll
    for (int i = 0; i < 9; i++) { r[i] = p[t + i*256] * scale; mx = fmaxf(mx, r[i]); }
    __shared__ float red[256];
    red[t] = mx; __syncthreads();
    for (int s = 128; s > 0; s >>= 1) { if (t < s) red[t] = fmaxf(red[t], red[t+s]); __syncthreads(); }
    mx = red[0];
    __syncthreads();
    float sum = 0.f;
    #pragma unroll
    for (int i = 0; i < 9; i++) { r[i] = __expf(r[i] - mx); sum += r[i]; }
    red[t] = sum; __syncthreads();
    for (int s = 128; s > 0; s >>= 1) { if (t < s) red[t] += red[t+s]; __syncthreads(); }
    const float inv = 1.f / red[0];
    #pragma unroll
    for (int i = 0; i < 9; i++) p[t + i*256] = r[i] * inv;
}

// ---------------- launch ----------------
extern "C" void kernel_launch(void* const* d_in, const int* in_sizes, int n_in,
                              void* d_out, int out_size) {
    (void)in_sizes; (void)n_in; (void)out_size;
    const float* front_x = (const float*)d_in[0];
    const float* bn1_g   = (const float*)d_in[1];
    const float* bn1_b   = (const float*)d_in[2];
    const float* tm1_w1  = (const float*)d_in[3];
    const float* tm1_b1  = (const float*)d_in[4];
    const float* tm1_w2  = (const float*)d_in[5];
    const float* tm1_b2  = (const float*)d_in[6];
    const float* q_w     = (const float*)d_in[7];
    const float* q_b     = (const float*)d_in[8];
    const float* k_w     = (const float*)d_in[9];
    const float* k_b     = (const float*)d_in[10];
    const float* v_w     = (const float*)d_in[11];
    const float* v_b     = (const float*)d_in[12];
    const float* m1_w    = (const float*)d_in[13];
    const float* m1_b    = (const float*)d_in[14];
    const float* bn2_g   = (const float*)d_in[15];
    const float* bn2_b   = (const float*)d_in[16];
    const float* tm2_w1  = (const float*)d_in[17];
    const float* tm2_b1  = (const float*)d_in[18];
    const float* tm2_w2  = (const float*)d_in[19];
    const float* tm2_b2  = (const float*)d_in[20];
    const float* m2_w    = (const float*)d_in[21];
    const float* m2_b    = (const float*)d_in[22];
    float* out = (float*)d_out;

    float *p_xn, *p_t1, *p_feat, *p_v, *p_V, *p_T, *p_fr, *p_q, *p_k, *p_E;
    cudaGetSymbolAddress((void**)&p_xn,  g_xn);
    cudaGetSymbolAddress((void**)&p_t1,  g_t1);
    cudaGetSymbolAddress((void**)&p_feat,g_feat);
    cudaGetSymbolAddress((void**)&p_v,   g_v);
    cudaGetSymbolAddress((void**)&p_V,   g_Vout);
    cudaGetSymbolAddress((void**)&p_T,   g_T);
    cudaGetSymbolAddress((void**)&p_fr,  g_fr);
    cudaGetSymbolAddress((void**)&p_q,   g_q);
    cudaGetSymbolAddress((void**)&p_k,   g_k);
    cudaGetSymbolAddress((void**)&p_E,   g_energy);

    cudaFuncSetAttribute(gemm_pipe_kernel<true>,  cudaFuncAttributeMaxDynamicSharedMemorySize, GSMEM);
    cudaFuncSetAttribute(gemm_pipe_kernel<false>, cudaFuncAttributeMaxDynamicSharedMemorySize, GSMEM);

    const dim3 gTM(NN/128, (BB*CC)/128, 1);
    const dim3 gE(NN/128, NN/128, BB);
    const dim3 gV(CC/128, NN/128, BB);
    const dim3 cgrid(NN/32, BB), cblk(32, 8);

    // stage 1: bn1 + tm1
    bn_stats_kernel<<<CC, 256>>>(front_x);
    bn_apply_kernel<<<BCN/256, 256>>>(front_x, bn1_g, bn1_b, p_xn);
    gemm_pipe_kernel<true><<<gTM, 256, GSMEM>>>(p_xn, tm1_w1, tm1_b1, p_t1, BB*CC, NN, NN, 0, 0, 0);
    gemm_pipe_kernel<true><<<gTM, 256, GSMEM>>>(p_t1, tm1_w2, tm1_b2, p_feat, BB*CC, NN, NN, 0, 0, 0);

    // q, k (stored transposed (B,N,16)), v (B,C,N)
    conv1x1_kernel<<<cgrid, cblk>>>(p_feat, nullptr, q_w, q_b, p_q, CC, 0, CQ, 1);
    conv1x1_kernel<<<cgrid, cblk>>>(p_feat, nullptr, k_w, k_b, p_k, CC, 0, CQ, 1);
    conv1x1_kernel<<<cgrid, cblk>>>(p_feat, nullptr, v_w, v_b, p_v, CC, 0, CC, 0);

    // attention: energy = Kt * Qt^T (K=16 -> legacy kernel), softmax(scale), Vout = energy * v^T
    gemm_abt_kernel<false><<<gE, 256>>>(p_k, p_q, nullptr, p_E, NN, NN, CQ,
                                        (size_t)NN*CQ, (size_t)NN*CQ, (size_t)NN*NN);
    softmax_kernel<<<BB*NN, 256>>>(p_E, 0.08838834764831845f);  // 1/sqrt(128)
    gemm_pipe_kernel<false><<<gV, 256, GSMEM>>>(p_E, p_v, nullptr, p_V, NN, CC, NN,
                                        (size_t)NN*NN, (size_t)CC*NN, (size_t)NN*CC);

    // m1 on concat(features, V)
    conv1x1_kernel<<<cgrid, cblk>>>(p_feat, p_V, m1_w, m1_b, p_T, CC, CC, CC, 0);

    // stage 2: bn2 + tm2
    bn_stats_kernel<<<CC, 256>>>(p_T);
    bn_apply_kernel<<<BCN/256, 256>>>(p_T, bn2_g, bn2_b, p_xn);
    gemm_pipe_kernel<true><<<gTM, 256, GSMEM>>>(p_xn, tm2_w1, tm2_b1, p_t1, BB*CC, NN, NN, 0, 0, 0);
    gemm_pipe_kernel<true><<<gTM, 256, GSMEM>>>(p_t1, tm2_w2, tm2_b2, p_fr, BB*CC, NN, NN, 0, 0, 0);

    // m2 on concat(front_res, V) -> output
    conv1x1_kernel<<<cgrid, cblk>>>(p_fr, p_V, m2_w, m2_b, out, CC, CC, CC, 0);
}

// round 8
// speedup vs baseline: 2.1499x; 2.1499x over previous
#include <cuda_runtime.h>
#include <cuda_fp16.h>
#include <mma.h>
#include <math.h>
#include <stdint.h>

using namespace nvcuda;

#define BB  16
#define CC  128
#define NN  2304
#define CQ  16
#define BCN (BB*CC*NN)

// ---------------- scratch (device globals) ----------------
__device__ float g_mean[CC], g_rstd[CC];
__device__ __half g_xnh[BCN];
__device__ __half g_t1h[BCN];
__device__ float  g_feat[BCN];
__device__ __half g_vh[BCN];                   // (B, C, N)
__device__ float  g_Vout[BCN];                 // (B, N, C)
__device__ float  g_T[BCN];
__device__ float  g_fr[BCN];
__device__ __half g_qh[BB*NN*CQ];              // (B, N, 16)
__device__ __half g_kh[BB*NN*CQ];
__device__ float  g_energy[(size_t)BB*NN*NN];  // ~340MB
__device__ __half g_probs[(size_t)BB*NN*NN];   // ~170MB
__device__ __half g_w1h[(size_t)NN*NN];
__device__ __half g_w2h[(size_t)NN*NN];
__device__ __half g_w3h[(size_t)NN*NN];
__device__ __half g_w4h[(size_t)NN*NN];

// ---------------- helpers ----------------
__device__ __forceinline__ uint32_t smem_u32(const void* p) {
    uint32_t a;
    asm("{ .reg .u64 t; cvta.to.shared.u64 t, %1; cvt.u32.u64 %0, t; }" : "=r"(a) : "l"(p));
    return a;
}
__device__ __forceinline__ void cp_async16(uint32_t s, const void* g) {
    asm volatile("cp.async.cg.shared.global [%0], [%1], 16;\n" :: "r"(s), "l"(g));
}
__device__ __forceinline__ void cp_commit() { asm volatile("cp.async.commit_group;\n"); }
template<int n> __device__ __forceinline__ void cp_wait() { asm volatile("cp.async.wait_group %0;\n" :: "n"(n)); }

// ================= fp16 GEMM: C[m,n] = op(sum_k A[m,k]*W[n,k] + bias[n]) =================
// A: (M,K) half row-major; W: (Nn,K) half row-major; K % 64 == 0.
// grid (Nn/128, M/128, batch), 256 threads (8 warps 2x4), double-buffered cp.async.
#define HST 18432            // bytes per matrix per stage: 128 rows * 144B (72 halves)
#define HSMEM (4*HST)        // 73728

template<bool RELU, bool OUTH>
__global__ __launch_bounds__(256, 2) void gemm_h_kernel(
    const __half* __restrict__ A, const __half* __restrict__ W,
    const float* __restrict__ bias, void* __restrict__ Cout,
    int Nn, int K, size_t sA, size_t sW, size_t sC)
{
    extern __shared__ char smem[];
    const int tid  = threadIdx.x;
    const int warp = tid >> 5, lane = tid & 31;
    const int wm = warp & 1;   // 2 warp-rows of 64
    const int wn = warp >> 1;  // 4 warp-cols of 32

    A += (size_t)blockIdx.z*sA + (size_t)blockIdx.y*128*(size_t)K;
    W += (size_t)blockIdx.z*sW + (size_t)blockIdx.x*128*(size_t)K;

    const uint32_t aA = smem_u32(smem);
    const uint32_t aB = aA + 2*HST;

    const int ktiles = K / 64;

    auto load_stage = [&](int kt) {
        const uint32_t so = (kt & 1) * HST;
        #pragma unroll
        for (int i = 0; i < 4; i++) {
            int idx = tid + i*256;          // 0..1023
            int row = idx >> 3;             // 0..127
            int c   = idx & 7;              // 16B chunk (8 halves)
            uint32_t off = so + row*144 + c*16;
            cp_async16(aA + off, A + (size_t)row*K + kt*64 + c*8);
            cp_async16(aB + off, W + (size_t)row*K + kt*64 + c*8);
        }
    };

    wmma::fragment<wmma::accumulator,16,16,16,float> acc[4][2];
    #pragma unroll
    for (int i = 0; i < 4; i++)
        #pragma unroll
        for (int j = 0; j < 2; j++)
            wmma::fill_fragment(acc[i][j], 0.f);

    load_stage(0);
    cp_commit();

    for (int kt = 0; kt < ktiles; kt++) {
        if (kt + 1 < ktiles) load_stage(kt + 1);
        cp_commit();
        cp_wait<1>();
        __syncthreads();
        const __half* As = (const __half*)(smem + (kt & 1)*HST);
        const __half* Ws = (const __half*)(smem + 2*HST + (kt & 1)*HST);
        #pragma unroll
        for (int ks = 0; ks < 4; ks++) {
            wmma::fragment<wmma::matrix_a,16,16,16,__half,wmma::row_major> af[4];
            wmma::fragment<wmma::matrix_b,16,16,16,__half,wmma::col_major> bf[2];
            #pragma unroll
            for (int i = 0; i < 4; i++)
                wmma::load_matrix_sync(af[i], As + (wm*64 + i*16)*72 + ks*16, 72);
            #pragma unroll
            for (int j = 0; j < 2; j++)
                wmma::load_matrix_sync(bf[j], Ws + (wn*32 + j*16)*72 + ks*16, 72);
            #pragma unroll
            for (int i = 0; i < 4; i++)
                #pragma unroll
                for (int j = 0; j < 2; j++)
                    wmma::mma_sync(acc[i][j], af[i], bf[j], acc[i][j]);
        }
        __syncthreads();
    }

    // ---- epilogue: stage 16x16 fragments through smem, vectorized stores ----
    float* st = (float*)smem + warp*256;
    const int row  = lane >> 1;
    const int half = lane & 1;
    const size_t crow0 = (size_t)blockIdx.y*128*(size_t)Nn + (size_t)blockIdx.x*128;
    float*  Cf = (float*) Cout + (size_t)blockIdx.z*sC + crow0;
    __half* Ch = (__half*)Cout + (size_t)blockIdx.z*sC + crow0;
    if (bias) bias += (size_t)blockIdx.x*128;

    #pragma unroll
    for (int i = 0; i < 4; i++) {
        #pragma unroll
        for (int j = 0; j < 2; j++) {
            wmma::store_matrix_sync(st, acc[i][j], 16, wmma::mem_row_major);
            __syncwarp();
            const int gr0 = wm*64 + i*16;
            const int gc0 = wn*32 + j*16;
            float4 v0 = *reinterpret_cast<const float4*>(st + row*16 + half*8);
            float4 v1 = *reinterpret_cast<const float4*>(st + row*16 + half*8 + 4);
            if (bias) {
                const float* bp = bias + gc0 + half*8;
                v0.x += bp[0]; v0.y += bp[1]; v0.z += bp[2]; v0.w += bp[3];
                v1.x += bp[4]; v1.y += bp[5]; v1.z += bp[6]; v1.w += bp[7];
            }
            if (RELU) {
                v0.x = fmaxf(v0.x, 0.f); v0.y = fmaxf(v0.y, 0.f); v0.z = fmaxf(v0.z, 0.f); v0.w = fmaxf(v0.w, 0.f);
                v1.x = fmaxf(v1.x, 0.f); v1.y = fmaxf(v1.y, 0.f); v1.z = fmaxf(v1.z, 0.f); v1.w = fmaxf(v1.w, 0.f);
            }
            const size_t o = (size_t)(gr0 + row)*Nn + gc0 + half*8;
            if (OUTH) {
                __half2 hh[4];
                hh[0] = __floats2half2_rn(v0.x, v0.y);
                hh[1] = __floats2half2_rn(v0.z, v0.w);
                hh[2] = __floats2half2_rn(v1.x, v1.y);
                hh[3] = __floats2half2_rn(v1.z, v1.w);
                *reinterpret_cast<uint4*>(Ch + o) = *reinterpret_cast<const uint4*>(hh);
            } else {
                *reinterpret_cast<float4*>(Cf + o)     = v0;
                *reinterpret_cast<float4*>(Cf + o + 4) = v1;
            }
            __syncwarp();
        }
    }
}

// ---------------- energy GEMM (K=16, fp16): E = Kt * Qt^T ----------------
__global__ __launch_bounds__(256) void energy_kernel(
    const __half* __restrict__ Kt, const __half* __restrict__ Qt,
    float* __restrict__ E)
{
    __shared__ __align__(16) char sm[2*128*24*2];   // 12KB, also reused for epilogue
    __half* As = (__half*)sm;
    __half* Ws = As + 128*24;

    const int tid  = threadIdx.x;
    const int warp = tid >> 5, lane = tid & 31;
    const int wm = warp & 1;
    const int wn = warp >> 1;

    Kt += (size_t)blockIdx.z*NN*CQ + (size_t)blockIdx.y*128*CQ;
    Qt += (size_t)blockIdx.z*NN*CQ + (size_t)blockIdx.x*128*CQ;
    E  += (size_t)blockIdx.z*NN*NN + (size_t)blockIdx.y*128*NN + (size_t)blockIdx.x*128;

    {
        int r = tid >> 1, c = (tid & 1)*8;
        *reinterpret_cast<uint4*>(As + r*24 + c) = *reinterpret_cast<const uint4*>(Kt + r*CQ + c);
        *reinterpret_cast<uint4*>(Ws + r*24 + c) = *reinterpret_cast<const uint4*>(Qt + r*CQ + c);
    }
    __syncthreads();

    wmma::fragment<wmma::accumulator,16,16,16,float> acc[4][2];
    wmma::fragment<wmma::matrix_a,16,16,16,__half,wmma::row_major> af[4];
    wmma::fragment<wmma::matrix_b,16,16,16,__half,wmma::col_major> bf[2];
    #pragma unroll
    for (int i = 0; i < 4; i++) {
        wmma::load_matrix_sync(af[i], As + (wm*64 + i*16)*24, 24);
        #pragma unroll
        for (int j = 0; j < 2; j++) wmma::fill_fragment(acc[i][j], 0.f);
    }
    #pragma unroll
    for (int j = 0; j < 2; j++)
        wmma::load_matrix_sync(bf[j], Ws + (wn*32 + j*16)*24, 24);
    #pragma unroll
    for (int i = 0; i < 4; i++)
        #pragma unroll
        for (int j = 0; j < 2; j++)
            wmma::mma_sync(acc[i][j], af[i], bf[j], acc[i][j]);

    __syncthreads();
    float* st = (float*)sm + warp*256;
    const int row  = lane >> 1;
    const int half = lane & 1;
    #pragma unroll
    for (int i = 0; i < 4; i++) {
        #pragma unroll
        for (int j = 0; j < 2; j++) {
            wmma::store_matrix_sync(st, acc[i][j], 16, wmma::mem_row_major);
            __syncwarp();
            const int gr0 = wm*64 + i*16;
            const int gc0 = wn*32 + j*16;
            float4 v0 = *reinterpret_cast<const float4*>(st + row*16 + half*8);
            float4 v1 = *reinterpret_cast<const float4*>(st + row*16 + half*8 + 4);
            float* op = E + (size_t)(gr0 + row)*NN + gc0 + half*8;
            *reinterpret_cast<float4*>(op)     = v0;
            *reinterpret_cast<float4*>(op + 4) = v1;
            __syncwarp();
        }
    }
}

// ---------------- weight fp32 -> fp16 ----------------
__global__ void tohalf_kernel(const float* __restrict__ in, __half* __restrict__ out) {
    size_t i = (size_t)blockIdx.x*256 + threadIdx.x;
    float4 v = *reinterpret_cast<const float4*>(in + i*4);
    __half2 hh[2];
    hh[0] = __floats2half2_rn(v.x, v.y);
    hh[1] = __floats2half2_rn(v.z, v.w);
    *reinterpret_cast<uint2*>(out + i*4) = *reinterpret_cast<const uint2*>(hh);
}

// ---------------- batchnorm ----------------
__global__ void bn_stats_kernel(const float* __restrict__ x) {
    int c = blockIdx.x;
    float s1 = 0.f, s2 = 0.f;
    for (int idx = threadIdx.x; idx < BB*NN; idx += 256) {
        int b = idx / NN, n = idx - b*NN;
        float v = x[((size_t)b*CC + c)*NN + n];
        s1 += v; s2 += v*v;
    }
    __shared__ float r1[256], r2[256];
    r1[threadIdx.x] = s1; r2[threadIdx.x] = s2;
    __syncthreads();
    for (int s = 128; s > 0; s >>= 1) {
        if (threadIdx.x < s) { r1[threadIdx.x] += r1[threadIdx.x+s]; r2[threadIdx.x] += r2[threadIdx.x+s]; }
        __syncthreads();
    }
    if (threadIdx.x == 0) {
        const float inv = 1.f / (float)(BB*NN);
        float m = r1[0] * inv;
        float var = r2[0] * inv - m*m;
        g_mean[c] = m;
        g_rstd[c] = rsqrtf(var + 1e-5f);
    }
}

__global__ void bn_apply_kernel(const float* __restrict__ x, const float* __restrict__ gam,
                                const float* __restrict__ bet, __half* __restrict__ y) {
    int idx = blockIdx.x*256 + threadIdx.x;
    int c = (idx / NN) % CC;
    float v = (x[idx] - g_mean[c]) * g_rstd[c] * gam[c] + bet[c];
    y[idx] = __float2half_rn(v);
}

// ---------------- conv1x1 ----------------
// X1: (B,Cin1,N) float. X2 (optional): (B,N,Cin2) float.
// out: OUTH ? half : float; outT ? (B,N,Cout) : (B,Cout,N)
template<bool OUTH>
__global__ __launch_bounds__(256) void conv1x1_kernel(
    const float* __restrict__ X1, const float* __restrict__ X2,
    const float* __restrict__ W, const float* __restrict__ bias,
    void* __restrict__ out, int Cin1, int Cin2, int Cout, int outT)
{
    __shared__ float s1[CC*33];
    __shared__ float s2[CC*33];
    const int b  = blockIdx.y;
    const int n0 = blockIdx.x * 32;
    const int tid = threadIdx.y*32 + threadIdx.x;

    for (int idx = tid; idx < Cin1*32; idx += 256) {
        int c = idx >> 5, n = idx & 31;
        s1[c*33 + n] = X1[((size_t)b*Cin1 + c)*NN + n0 + n];
    }
    if (X2) {
        for (int idx = tid; idx < 32*Cin2; idx += 256) {
            int n = idx >> 7, c = idx & 127;
            s2[c*33 + n] = X2[((size_t)b*NN + n0 + n)*(size_t)Cin2 + c];
        }
    }
    __syncthreads();

    const int nx = threadIdx.x, ty = threadIdx.y;
    const int Ct = Cin1 + Cin2;
    float*  outF = (float*)out;
    __half* outH = (__half*)out;
    for (int ob = 0; ob < Cout; ob += 32) {
        const int nacc = (Cout - ob) >= 32 ? 4 : ((Cout - ob + 7) >> 3);
        float acc[4];
        #pragma unroll
        for (int u = 0; u < 4; u++) acc[u] = (u < nacc) ? bias[ob + ty + 8*u] : 0.f;
        for (int c = 0; c < Cin1; c++) {
            float xv = s1[c*33 + nx];
            #pragma unroll
            for (int u = 0; u < 4; u++)
                if (u < nacc) acc[u] += W[(size_t)(ob + ty + 8*u)*Ct + c] * xv;
        }
        if (X2) {
            for (int c = 0; c < Cin2; c++) {
                float xv = s2[c*33 + nx];
                #pragma unroll
                for (int u = 0; u < 4; u++)
                    if (u < nacc) acc[u] += W[(size_t)(ob + ty + 8*u)*Ct + Cin1 + c] * xv;
            }
        }
        #pragma unroll
        for (int u = 0; u < 4; u++) if (u < nacc) {
            int o = ob + ty + 8*u;
            size_t oi = outT ? ((size_t)b*NN + n0 + nx)*(size_t)Cout + o
                             : ((size_t)b*Cout + o)*(size_t)NN + n0 + nx;
            if (OUTH) outH[oi] = __float2half_rn(acc[u]);
            else      outF[oi] = acc[u];
        }
    }
}

// ---------------- row softmax (pre-scale), fp16 probs out ----------------
__global__ void softmax_kernel(const float* __restrict__ E, __half* __restrict__ P, float scale) {
    const float* p = E + (size_t)blockIdx.x * NN;
    __half* q = P + (size_t)blockIdx.x * NN;
    const int t = threadIdx.x;
    float r[9];
    float mx = -1e30f;
    #pragma unroll
    for (int i = 0; i < 9; i++) { r[i] = p[t + i*256] * scale; mx = fmaxf(mx, r[i]); }
    __shared__ float red[256];
    red[t] = mx; __syncthreads();
    for (int s = 128; s > 0; s >>= 1) { if (t < s) red[t] = fmaxf(red[t], red[t+s]); __syncthreads(); }
    mx = red[0];
    __syncthreads();
    float sum = 0.f;
    #pragma unroll
    for (int i = 0; i < 9; i++) { r[i] = __expf(r[i] - mx); sum += r[i]; }
    red[t] = sum; __syncthreads();
    for (int s = 128; s > 0; s >>= 1) { if (t < s) red[t] += red[t+s]; __syncthreads(); }
    const float inv = 1.f / red[0];
    #pragma unroll
    for (int i = 0; i < 9; i++) q[t + i*256] = __float2half_rn(r[i] * inv);
}

// ---------------- launch ----------------
extern "C" void kernel_launch(void* const* d_in, const int* in_sizes, int n_in,
                              void* d_out, int out_size) {
    (void)in_sizes; (void)n_in; (void)out_size;
    const float* front_x = (const float*)d_in[0];
    const float* bn1_g   = (const float*)d_in[1];
    const float* bn1_b   = (const float*)d_in[2];
    const float* tm1_w1  = (const float*)d_in[3];
    const float* tm1_b1  = (const float*)d_in[4];
    const float* tm1_w2  = (const float*)d_in[5];
    const float* tm1_b2  = (const float*)d_in[6];
    const float* q_w     = (const float*)d_in[7];
    const float* q_b     = (const float*)d_in[8];
    const float* k_w     = (const float*)d_in[9];
    const float* k_b     = (const float*)d_in[10];
    const float* v_w     = (const float*)d_in[11];
    const float* v_b     = (const float*)d_in[12];
    const float* m1_w    = (const float*)d_in[13];
    const float* m1_b    = (const float*)d_in[14];
    const float* bn2_g   = (const float*)d_in[15];
    const float* bn2_b   = (const float*)d_in[16];
    const float* tm2_w1  = (const float*)d_in[17];
    const float* tm2_b1  = (const float*)d_in[18];
    const float* tm2_w2  = (const float*)d_in[19];
    const float* tm2_b2  = (const float*)d_in[20];
    const float* m2_w    = (const float*)d_in[21];
    const float* m2_b    = (const float*)d_in[22];
    float* out = (float*)d_out;

    __half *p_xnh, *p_t1h, *p_vh, *p_qh, *p_kh, *p_probs, *p_w1, *p_w2, *p_w3, *p_w4;
    float  *p_feat, *p_V, *p_T, *p_fr, *p_E;
    cudaGetSymbolAddress((void**)&p_xnh,  g_xnh);
    cudaGetSymbolAddress((void**)&p_t1h,  g_t1h);
    cudaGetSymbolAddress((void**)&p_feat, g_feat);
    cudaGetSymbolAddress((void**)&p_vh,   g_vh);
    cudaGetSymbolAddress((void**)&p_V,    g_Vout);
    cudaGetSymbolAddress((void**)&p_T,    g_T);
    cudaGetSymbolAddress((void**)&p_fr,   g_fr);
    cudaGetSymbolAddress((void**)&p_qh,   g_qh);
    cudaGetSymbolAddress((void**)&p_kh,   g_kh);
    cudaGetSymbolAddress((void**)&p_E,    g_energy);
    cudaGetSymbolAddress((void**)&p_probs,g_probs);
    cudaGetSymbolAddress((void**)&p_w1,   g_w1h);
    cudaGetSymbolAddress((void**)&p_w2,   g_w2h);
    cudaGetSymbolAddress((void**)&p_w3,   g_w3h);
    cudaGetSymbolAddress((void**)&p_w4,   g_w4h);

    cudaFuncSetAttribute(gemm_h_kernel<true,true>,   cudaFuncAttributeMaxDynamicSharedMemorySize, HSMEM);
    cudaFuncSetAttribute(gemm_h_kernel<true,false>,  cudaFuncAttributeMaxDynamicSharedMemorySize, HSMEM);
    cudaFuncSetAttribute(gemm_h_kernel<false,false>, cudaFuncAttributeMaxDynamicSharedMemorySize, HSMEM);

    const dim3 gTM(NN/128, (BB*CC)/128, 1);      // 18 x 16
    const dim3 gVg(1, NN/128, BB);               // 1 x 18 x 16
    const dim3 gE(NN/128, NN/128, BB);
    const dim3 cgrid(NN/32, BB), cblk(32, 8);
    const int wblk = (NN*NN)/(256*4);

    // weights fp32 -> fp16
    tohalf_kernel<<<wblk, 256>>>(tm1_w1, p_w1);
    tohalf_kernel<<<wblk, 256>>>(tm1_w2, p_w2);
    tohalf_kernel<<<wblk, 256>>>(tm2_w1, p_w3);
    tohalf_kernel<<<wblk, 256>>>(tm2_w2, p_w4);

    // stage 1: bn1 + tm1
    bn_stats_kernel<<<CC, 256>>>(front_x);
    bn_apply_kernel<<<BCN/256, 256>>>(front_x, bn1_g, bn1_b, p_xnh);
    gemm_h_kernel<true,true ><<<gTM, 256, HSMEM>>>(p_xnh, p_w1, tm1_b1, p_t1h, NN, NN, 0, 0, 0);
    gemm_h_kernel<true,false><<<gTM, 256, HSMEM>>>(p_t1h, p_w2, tm1_b2, p_feat, NN, NN, 0, 0, 0);

    // q, k transposed (B,N,16) half; v (B,C,N) half
    conv1x1_kernel<true><<<cgrid, cblk>>>(p_feat, nullptr, q_w, q_b, p_qh, CC, 0, CQ, 1);
    conv1x1_kernel<true><<<cgrid, cblk>>>(p_feat, nullptr, k_w, k_b, p_kh, CC, 0, CQ, 1);
    conv1x1_kernel<true><<<cgrid, cblk>>>(p_feat, nullptr, v_w, v_b, p_vh, CC, 0, CC, 0);

    // attention
    energy_kernel<<<gE, 256>>>(p_kh, p_qh, p_E);
    softmax_kernel<<<BB*NN, 256>>>(p_E, p_probs, 0.08838834764831845f);
    gemm_h_kernel<false,false><<<gVg, 256, HSMEM>>>(p_probs, p_vh, nullptr, p_V, CC, NN,
                                 (size_t)NN*NN, (size_t)CC*NN, (size_t)NN*CC);

    // m1 on concat(features, V)
    conv1x1_kernel<false><<<cgrid, cblk>>>(p_feat, p_V, m1_w, m1_b, p_T, CC, CC, CC, 0);

    // stage 2: bn2 + tm2
    bn_stats_kernel<<<CC, 256>>>(p_T);
    bn_apply_kernel<<<BCN/256, 256>>>(p_T, bn2_g, bn2_b, p_xnh);
    gemm_h_kernel<true,true ><<<gTM, 256, HSMEM>>>(p_xnh, p_w3, tm2_b1, p_t1h, NN, NN, 0, 0, 0);
    gemm_h_kernel<true,false><<<gTM, 256, HSMEM>>>(p_t1h, p_w4, tm2_b2, p_fr, NN, NN, 0, 0, 0);

    // m2 on concat(front_res, V) -> output
    conv1x1_kernel<false><<<cgrid, cblk>>>(p_fr, p_V, m2_w, m2_b, out, CC, CC, CC, 0);
}

// round 9
// speedup vs baseline: 2.2345x; 1.0394x over previous
#include <cuda_runtime.h>
#include <cuda_fp16.h>
#include <mma.h>
#include <math.h>
#include <stdint.h>

using namespace nvcuda;

#define BB  16
#define CC  128
#define NN  2304
#define CQ  16
#define BCN (BB*CC*NN)
#define ATILE (NN/128)   // 18

// ---------------- scratch (device globals) ----------------
__device__ float g_mean[CC], g_rstd[CC];
__device__ __half g_xnh[BCN];
__device__ __half g_t1h[BCN];
__device__ float  g_feat[BCN];
__device__ __half g_vh[BCN];                   // (B, C, N)
__device__ float  g_Vout[BCN];                 // (B, N, C)
__device__ float  g_T[BCN];
__device__ float  g_fr[BCN];
__device__ __half g_qh[BB*NN*CQ];              // (B, N, 16), pre-scaled by 1/sqrt(C)
__device__ __half g_kh[BB*NN*CQ];
__device__ __half g_probs[(size_t)BB*NN*NN];   // unnormalized exp(e-m), ~170MB
__device__ float  g_rsum[BB*NN];               // per-row 1/sum
__device__ __half g_w1h[(size_t)NN*NN];
__device__ __half g_w2h[(size_t)NN*NN];
__device__ __half g_w3h[(size_t)NN*NN];
__device__ __half g_w4h[(size_t)NN*NN];

// ---------------- helpers ----------------
__device__ __forceinline__ uint32_t smem_u32(const void* p) {
    uint32_t a;
    asm("{ .reg .u64 t; cvta.to.shared.u64 t, %1; cvt.u32.u64 %0, t; }" : "=r"(a) : "l"(p));
    return a;
}
__device__ __forceinline__ void cp_async16(uint32_t s, const void* g) {
    asm volatile("cp.async.cg.shared.global [%0], [%1], 16;\n" :: "r"(s), "l"(g));
}
__device__ __forceinline__ void cp_commit() { asm volatile("cp.async.commit_group;\n"); }
template<int n> __device__ __forceinline__ void cp_wait() { asm volatile("cp.async.wait_group %0;\n" :: "n"(n)); }

// ================= fp16 GEMM: C[m,n] = op(rowscale[m] * (sum_k A[m,k]*W[n,k] + bias[n])) ========
#define HST 18432            // bytes per matrix per stage: 128 rows * 144B (72 halves)
#define HSMEM (4*HST)        // 73728

template<bool RELU, bool OUTH>
__global__ __launch_bounds__(256, 2) void gemm_h_kernel(
    const __half* __restrict__ A, const __half* __restrict__ W,
    const float* __restrict__ bias, void* __restrict__ Cout,
    int Nn, int K, size_t sA, size_t sW, size_t sC,
    const float* __restrict__ rowscale)
{
    extern __shared__ char smem[];
    const int tid  = threadIdx.x;
    const int warp = tid >> 5, lane = tid & 31;
    const int wm = warp & 1;   // 2 warp-rows of 64
    const int wn = warp >> 1;  // 4 warp-cols of 32

    A += (size_t)blockIdx.z*sA + (size_t)blockIdx.y*128*(size_t)K;
    W += (size_t)blockIdx.z*sW + (size_t)blockIdx.x*128*(size_t)K;

    const uint32_t aA = smem_u32(smem);
    const uint32_t aB = aA + 2*HST;

    const int ktiles = K / 64;

    auto load_stage = [&](int kt) {
        const uint32_t so = (kt & 1) * HST;
        #pragma unroll
        for (int i = 0; i < 4; i++) {
            int idx = tid + i*256;          // 0..1023
            int row = idx >> 3;             // 0..127
            int c   = idx & 7;              // 16B chunk (8 halves)
            uint32_t off = so + row*144 + c*16;
            cp_async16(aA + off, A + (size_t)row*K + kt*64 + c*8);
            cp_async16(aB + off, W + (size_t)row*K + kt*64 + c*8);
        }
    };

    wmma::fragment<wmma::accumulator,16,16,16,float> acc[4][2];
    #pragma unroll
    for (int i = 0; i < 4; i++)
        #pragma unroll
        for (int j = 0; j < 2; j++)
            wmma::fill_fragment(acc[i][j], 0.f);

    load_stage(0);
    cp_commit();

    for (int kt = 0; kt < ktiles; kt++) {
        if (kt + 1 < ktiles) load_stage(kt + 1);
        cp_commit();
        cp_wait<1>();
        __syncthreads();
        const __half* As = (const __half*)(smem + (kt & 1)*HST);
        const __half* Ws = (const __half*)(smem + 2*HST + (kt & 1)*HST);
        #pragma unroll
        for (int ks = 0; ks < 4; ks++) {
            wmma::fragment<wmma::matrix_a,16,16,16,__half,wmma::row_major> af[4];
            wmma::fragment<wmma::matrix_b,16,16,16,__half,wmma::col_major> bf[2];
            #pragma unroll
            for (int i = 0; i < 4; i++)
                wmma::load_matrix_sync(af[i], As + (wm*64 + i*16)*72 + ks*16, 72);
            #pragma unroll
            for (int j = 0; j < 2; j++)
                wmma::load_matrix_sync(bf[j], Ws + (wn*32 + j*16)*72 + ks*16, 72);
            #pragma unroll
            for (int i = 0; i < 4; i++)
                #pragma unroll
                for (int j = 0; j < 2; j++)
                    wmma::mma_sync(acc[i][j], af[i], bf[j], acc[i][j]);
        }
        __syncthreads();
    }

    // ---- epilogue ----
    float* st = (float*)smem + warp*256;
    const int row  = lane >> 1;
    const int half = lane & 1;
    const size_t crow0 = (size_t)blockIdx.y*128*(size_t)Nn + (size_t)blockIdx.x*128;
    float*  Cf = (float*) Cout + (size_t)blockIdx.z*sC + crow0;
    __half* Ch = (__half*)Cout + (size_t)blockIdx.z*sC + crow0;
    if (bias) bias += (size_t)blockIdx.x*128;
    const int Mtot = gridDim.y * 128;

    #pragma unroll
    for (int i = 0; i < 4; i++) {
        #pragma unroll
        for (int j = 0; j < 2; j++) {
            wmma::store_matrix_sync(st, acc[i][j], 16, wmma::mem_row_major);
            __syncwarp();
            const int gr0 = wm*64 + i*16;
            const int gc0 = wn*32 + j*16;
            float4 v0 = *reinterpret_cast<const float4*>(st + row*16 + half*8);
            float4 v1 = *reinterpret_cast<const float4*>(st + row*16 + half*8 + 4);
            if (bias) {
                const float* bp = bias + gc0 + half*8;
                v0.x += bp[0]; v0.y += bp[1]; v0.z += bp[2]; v0.w += bp[3];
                v1.x += bp[4]; v1.y += bp[5]; v1.z += bp[6]; v1.w += bp[7];
            }
            if (rowscale) {
                float sc = rowscale[(size_t)blockIdx.z*Mtot + blockIdx.y*128 + gr0 + row];
                v0.x *= sc; v0.y *= sc; v0.z *= sc; v0.w *= sc;
                v1.x *= sc; v1.y *= sc; v1.z *= sc; v1.w *= sc;
            }
            if (RELU) {
                v0.x = fmaxf(v0.x, 0.f); v0.y = fmaxf(v0.y, 0.f); v0.z = fmaxf(v0.z, 0.f); v0.w = fmaxf(v0.w, 0.f);
                v1.x = fmaxf(v1.x, 0.f); v1.y = fmaxf(v1.y, 0.f); v1.z = fmaxf(v1.z, 0.f); v1.w = fmaxf(v1.w, 0.f);
            }
            const size_t o = (size_t)(gr0 + row)*Nn + gc0 + half*8;
            if (OUTH) {
                __half2 hh[4];
                hh[0] = __floats2half2_rn(v0.x, v0.y);
                hh[1] = __floats2half2_rn(v0.z, v0.w);
                hh[2] = __floats2half2_rn(v1.x, v1.y);
                hh[3] = __floats2half2_rn(v1.z, v1.w);
                *reinterpret_cast<uint4*>(Ch + o) = *reinterpret_cast<const uint4*>(hh);
            } else {
                *reinterpret_cast<float4*>(Cf + o)     = v0;
                *reinterpret_cast<float4*>(Cf + o + 4) = v1;
            }
            __syncwarp();
        }
    }
}

// ============= fused energy + softmax: P[b,i,j] = exp(s*KtQt - rowmax), rsum_inv[b,i] ============
// q is pre-scaled by 1/sqrt(C). grid (ATILE, B), 256 threads.
// Pass A: compute S tiles (wmma), track row max. Pass B: recompute, exp, row sum, write fp16.
#define ASMEM (2*128*24*2 + 128*132*4 + 128*4)   // sK + sQ + sS + sM = 80384

__global__ __launch_bounds__(256) void attn_kernel(
    const __half* __restrict__ Kt, const __half* __restrict__ Qt,
    __half* __restrict__ P, float* __restrict__ rsum_inv)
{
    extern __shared__ char smraw[];
    __half* sK = (__half*)smraw;             // 128 x 24
    __half* sQ = sK + 128*24;                // 128 x 24
    float*  sS = (float*)(sQ + 128*24);      // 128 x 132
    float*  sM = sS + 128*132;               // 128

    const int tid  = threadIdx.x;
    const int warp = tid >> 5;
    const int wm = warp & 1, wn = warp >> 1;
    const int b  = blockIdx.y;
    const int i0 = blockIdx.x * 128;

    Kt += ((size_t)b*NN + i0) * CQ;
    Qt += (size_t)b*NN*CQ;
    P  += ((size_t)b*NN + i0) * NN;

    {   // load K block (128 rows x 16 halves)
        int r = tid >> 1, c = (tid & 1)*8;
        *reinterpret_cast<uint4*>(sK + r*24 + c) = *reinterpret_cast<const uint4*>(Kt + r*CQ + c);
    }
    __syncthreads();

    wmma::fragment<wmma::matrix_a,16,16,16,__half,wmma::row_major> af[4];
    #pragma unroll
    for (int i = 0; i < 4; i++)
        wmma::load_matrix_sync(af[i], sK + (wm*64 + i*16)*24, 24);

    const int rr = tid >> 1;          // row this thread pair handles
    const int ch = (tid & 1) * 64;    // col half base

    float lm = -1e30f;
    float ls = 0.f;

    for (int pass = 0; pass < 2; pass++) {
        for (int jt = 0; jt < ATILE; jt++) {
            {   // load Q tile
                int r = tid >> 1, c = (tid & 1)*8;
                *reinterpret_cast<uint4*>(sQ + r*24 + c) =
                    *reinterpret_cast<const uint4*>(Qt + (size_t)(jt*128 + r)*CQ + c);
            }
            __syncthreads();
            wmma::fragment<wmma::matrix_b,16,16,16,__half,wmma::col_major> bf[2];
            wmma::fragment<wmma::accumulator,16,16,16,float> acc[4][2];
            #pragma unroll
            for (int j = 0; j < 2; j++)
                wmma::load_matrix_sync(bf[j], sQ + (wn*32 + j*16)*24, 24);
            #pragma unroll
            for (int i = 0; i < 4; i++)
                #pragma unroll
                for (int j = 0; j < 2; j++) {
                    wmma::fill_fragment(acc[i][j], 0.f);
                    wmma::mma_sync(acc[i][j], af[i], bf[j], acc[i][j]);
                }
            #pragma unroll
            for (int i = 0; i < 4; i++)
                #pragma unroll
                for (int j = 0; j < 2; j++)
                    wmma::store_matrix_sync(sS + (wm*64 + i*16)*132 + wn*32 + j*16,
                                            acc[i][j], 132, wmma::mem_row_major);
            __syncthreads();

            if (pass == 0) {
                const float* row = sS + rr*132 + ch;
                #pragma unroll 16
                for (int c = 0; c < 64; c++) lm = fmaxf(lm, row[c]);
            } else {
                const float m = sM[rr];
                float* row = sS + rr*132 + ch;
                #pragma unroll 8
                for (int c = 0; c < 64; c++) {
                    float p = __expf(row[c] - m);
                    ls += p;
                    row[c] = p;
                }
                __syncthreads();
                // cooperative coalesced half2 writes
                for (int e = tid; e < 128*64; e += 256) {
                    int r = e >> 6, c2 = (e & 63)*2;
                    __half2 h = __floats2half2_rn(sS[r*132 + c2], sS[r*132 + c2 + 1]);
                    *reinterpret_cast<__half2*>(P + (size_t)r*NN + jt*128 + c2) = h;
                }
            }
            __syncthreads();
        }
        if (pass == 0) {
            float o = __shfl_xor_sync(0xffffffffu, lm, 1);
            lm = fmaxf(lm, o);
            if ((tid & 1) == 0) sM[rr] = lm;
            __syncthreads();
        } else {
            float o = __shfl_xor_sync(0xffffffffu, ls, 1);
            ls += o;
            if ((tid & 1) == 0) rsum_inv[(size_t)b*NN + i0 + rr] = 1.f / ls;
        }
    }
}

// ---------------- weight fp32 -> fp16 ----------------
__global__ void tohalf_kernel(const float* __restrict__ in, __half* __restrict__ out) {
    size_t i = (size_t)blockIdx.x*256 + threadIdx.x;
    float4 v = *reinterpret_cast<const float4*>(in + i*4);
    __half2 hh[2];
    hh[0] = __floats2half2_rn(v.x, v.y);
    hh[1] = __floats2half2_rn(v.z, v.w);
    *reinterpret_cast<uint2*>(out + i*4) = *reinterpret_cast<const uint2*>(hh);
}

// ---------------- batchnorm ----------------
__global__ void bn_stats_kernel(const float* __restrict__ x) {
    int c = blockIdx.x;
    float s1 = 0.f, s2 = 0.f;
    for (int idx = threadIdx.x; idx < BB*NN; idx += 256) {
        int b = idx / NN, n = idx - b*NN;
        float v = x[((size_t)b*CC + c)*NN + n];
        s1 += v; s2 += v*v;
    }
    __shared__ float r1[256], r2[256];
    r1[threadIdx.x] = s1; r2[threadIdx.x] = s2;
    __syncthreads();
    for (int s = 128; s > 0; s >>= 1) {
        if (threadIdx.x < s) { r1[threadIdx.x] += r1[threadIdx.x+s]; r2[threadIdx.x] += r2[threadIdx.x+s]; }
        __syncthreads();
    }
    if (threadIdx.x == 0) {
        const float inv = 1.f / (float)(BB*NN);
        float m = r1[0] * inv;
        float var = r2[0] * inv - m*m;
        g_mean[c] = m;
        g_rstd[c] = rsqrtf(var + 1e-5f);
    }
}

__global__ void bn_apply_kernel(const float* __restrict__ x, const float* __restrict__ gam,
                                const float* __restrict__ bet, __half* __restrict__ y) {
    int idx = blockIdx.x*256 + threadIdx.x;
    int c = (idx / NN) % CC;
    float v = (x[idx] - g_mean[c]) * g_rstd[c] * gam[c] + bet[c];
    y[idx] = __float2half_rn(v);
}

// ---------------- conv1x1 ----------------
template<bool OUTH>
__global__ __launch_bounds__(256) void conv1x1_kernel(
    const float* __restrict__ X1, const float* __restrict__ X2,
    const float* __restrict__ W, const float* __restrict__ bias,
    void* __restrict__ out, int Cin1, int Cin2, int Cout, int outT, float oscale)
{
    __shared__ float s1[CC*33];
    __shared__ float s2[CC*33];
    const int b  = blockIdx.y;
    const int n0 = blockIdx.x * 32;
    const int tid = threadIdx.y*32 + threadIdx.x;

    for (int idx = tid; idx < Cin1*32; idx += 256) {
        int c = idx >> 5, n = idx & 31;
        s1[c*33 + n] = X1[((size_t)b*Cin1 + c)*NN + n0 + n];
    }
    if (X2) {
        for (int idx = tid; idx < 32*Cin2; idx += 256) {
            int n = idx >> 7, c = idx & 127;
            s2[c*33 + n] = X2[((size_t)b*NN + n0 + n)*(size_t)Cin2 + c];
        }
    }
    __syncthreads();

    const int nx = threadIdx.x, ty = threadIdx.y;
    const int Ct = Cin1 + Cin2;
    float*  outF = (float*)out;
    __half* outH = (__half*)out;
    for (int ob = 0; ob < Cout; ob += 32) {
        const int nacc = (Cout - ob) >= 32 ? 4 : ((Cout - ob + 7) >> 3);
        float acc[4];
        #pragma unroll
        for (int u = 0; u < 4; u++) acc[u] = (u < nacc) ? bias[ob + ty + 8*u] : 0.f;
        for (int c = 0; c < Cin1; c++) {
            float xv = s1[c*33 + nx];
            #pragma unroll
            for (int u = 0; u < 4; u++)
                if (u < nacc) acc[u] += W[(size_t)(ob + ty + 8*u)*Ct + c] * xv;
        }
        if (X2) {
            for (int c = 0; c < Cin2; c++) {
                float xv = s2[c*33 + nx];
                #pragma unroll
                for (int u = 0; u < 4; u++)
                    if (u < nacc) acc[u] += W[(size_t)(ob + ty + 8*u)*Ct + Cin1 + c] * xv;
            }
        }
        #pragma unroll
        for (int u = 0; u < 4; u++) if (u < nacc) {
            int o = ob + ty + 8*u;
            size_t oi = outT ? ((size_t)b*NN + n0 + nx)*(size_t)Cout + o
                             : ((size_t)b*Cout + o)*(size_t)NN + n0 + nx;
            if (OUTH) outH[oi] = __float2half_rn(acc[u] * oscale);
            else      outF[oi] = acc[u] * oscale;
        }
    }
}

// ---------------- launch ----------------
extern "C" void kernel_launch(void* const* d_in, const int* in_sizes, int n_in,
                              void* d_out, int out_size) {
    (void)in_sizes; (void)n_in; (void)out_size;
    const float* front_x = (const float*)d_in[0];
    const float* bn1_g   = (const float*)d_in[1];
    const float* bn1_b   = (const float*)d_in[2];
    const float* tm1_w1  = (const float*)d_in[3];
    const float* tm1_b1  = (const float*)d_in[4];
    const float* tm1_w2  = (const float*)d_in[5];
    const float* tm1_b2  = (const float*)d_in[6];
    const float* q_w     = (const float*)d_in[7];
    const float* q_b     = (const float*)d_in[8];
    const float* k_w     = (const float*)d_in[9];
    const float* k_b     = (const float*)d_in[10];
    const float* v_w     = (const float*)d_in[11];
    const float* v_b     = (const float*)d_in[12];
    const float* m1_w    = (const float*)d_in[13];
    const float* m1_b    = (const float*)d_in[14];
    const float* bn2_g   = (const float*)d_in[15];
    const float* bn2_b   = (const float*)d_in[16];
    const float* tm2_w1  = (const float*)d_in[17];
    const float* tm2_b1  = (const float*)d_in[18];
    const float* tm2_w2  = (const float*)d_in[19];
    const float* tm2_b2  = (const float*)d_in[20];
    const float* m2_w    = (const float*)d_in[21];
    const float* m2_b    = (const float*)d_in[22];
    float* out = (float*)d_out;

    __half *p_xnh, *p_t1h, *p_vh, *p_qh, *p_kh, *p_probs, *p_w1, *p_w2, *p_w3, *p_w4;
    float  *p_feat, *p_V, *p_T, *p_fr, *p_rsum;
    cudaGetSymbolAddress((void**)&p_xnh,  g_xnh);
    cudaGetSymbolAddress((void**)&p_t1h,  g_t1h);
    cudaGetSymbolAddress((void**)&p_feat, g_feat);
    cudaGetSymbolAddress((void**)&p_vh,   g_vh);
    cudaGetSymbolAddress((void**)&p_V,    g_Vout);
    cudaGetSymbolAddress((void**)&p_T,    g_T);
    cudaGetSymbolAddress((void**)&p_fr,   g_fr);
    cudaGetSymbolAddress((void**)&p_qh,   g_qh);
    cudaGetSymbolAddress((void**)&p_kh,   g_kh);
    cudaGetSymbolAddress((void**)&p_probs,g_probs);
    cudaGetSymbolAddress((void**)&p_rsum, g_rsum);
    cudaGetSymbolAddress((void**)&p_w1,   g_w1h);
    cudaGetSymbolAddress((void**)&p_w2,   g_w2h);
    cudaGetSymbolAddress((void**)&p_w3,   g_w3h);
    cudaGetSymbolAddress((void**)&p_w4,   g_w4h);

    cudaFuncSetAttribute(gemm_h_kernel<true,true>,   cudaFuncAttributeMaxDynamicSharedMemorySize, HSMEM);
    cudaFuncSetAttribute(gemm_h_kernel<true,false>,  cudaFuncAttributeMaxDynamicSharedMemorySize, HSMEM);
    cudaFuncSetAttribute(gemm_h_kernel<false,false>, cudaFuncAttributeMaxDynamicSharedMemorySize, HSMEM);
    cudaFuncSetAttribute(attn_kernel, cudaFuncAttributeMaxDynamicSharedMemorySize, ASMEM);

    const dim3 gTM(NN/128, (BB*CC)/128, 1);      // 18 x 16
    const dim3 gVg(1, NN/128, BB);               // 1 x 18 x 16
    const dim3 gA(ATILE, BB);                    // 18 x 16
    const dim3 cgrid(NN/32, BB), cblk(32, 8);
    const int wblk = (NN*NN)/(256*4);
    const float qscale = 0.08838834764831845f;   // 1/sqrt(128)

    // weights fp32 -> fp16
    tohalf_kernel<<<wblk, 256>>>(tm1_w1, p_w1);
    tohalf_kernel<<<wblk, 256>>>(tm1_w2, p_w2);
    tohalf_kernel<<<wblk, 256>>>(tm2_w1, p_w3);
    tohalf_kernel<<<wblk, 256>>>(tm2_w2, p_w4);

    // stage 1: bn1 + tm1
    bn_stats_kernel<<<CC, 256>>>(front_x);
    bn_apply_kernel<<<BCN/256, 256>>>(front_x, bn1_g, bn1_b, p_xnh);
    gemm_h_kernel<true,true ><<<gTM, 256, HSMEM>>>(p_xnh, p_w1, tm1_b1, p_t1h, NN, NN, 0, 0, 0, nullptr);
    gemm_h_kernel<true,false><<<gTM, 256, HSMEM>>>(p_t1h, p_w2, tm1_b2, p_feat, NN, NN, 0, 0, 0, nullptr);

    // q (pre-scaled), k transposed (B,N,16) half; v (B,C,N) half
    conv1x1_kernel<true><<<cgrid, cblk>>>(p_feat, nullptr, q_w, q_b, p_qh, CC, 0, CQ, 1, qscale);
    conv1x1_kernel<true><<<cgrid, cblk>>>(p_feat, nullptr, k_w, k_b, p_kh, CC, 0, CQ, 1, 1.f);
    conv1x1_kernel<true><<<cgrid, cblk>>>(p_feat, nullptr, v_w, v_b, p_vh, CC, 0, CC, 0, 1.f);

    // fused attention energy+softmax -> unnormalized fp16 probs + row inv-sums
    attn_kernel<<<gA, 256, ASMEM>>>(p_kh, p_qh, p_probs, p_rsum);
    // V aggregation with per-row normalization in epilogue
    gemm_h_kernel<false,false><<<gVg, 256, HSMEM>>>(p_probs, p_vh, nullptr, p_V, CC, NN,
                                 (size_t)NN*NN, (size_t)CC*NN, (size_t)NN*CC, p_rsum);

    // m1 on concat(features, V)
    conv1x1_kernel<false><<<cgrid, cblk>>>(p_feat, p_V, m1_w, m1_b, p_T, CC, CC, CC, 0, 1.f);

    // stage 2: bn2 + tm2
    bn_stats_kernel<<<CC, 256>>>(p_T);
    bn_apply_kernel<<<BCN/256, 256>>>(p_T, bn2_g, bn2_b, p_xnh);
    gemm_h_kernel<true,true ><<<gTM, 256, HSMEM>>>(p_xnh, p_w3, tm2_b1, p_t1h, NN, NN, 0, 0, 0, nullptr);
    gemm_h_kernel<true,false><<<gTM, 256, HSMEM>>>(p_t1h, p_w4, tm2_b2, p_fr, NN, NN, 0, 0, 0, nullptr);

    // m2 on concat(front_res, V) -> output
    conv1x1_kernel<false><<<cgrid, cblk>>>(p_fr, p_V, m2_w, m2_b, out, CC, CC, CC, 0, 1.f);
}